// round 9
// baseline (speedup 1.0000x reference)
#include <cuda_runtime.h>

// Problem constants (fixed-shape problem)
#define NVOC 100     // vocab
#define NL   5       // layers
#define NH   32      // hidden of gate MLP
#define NSD  16      // s-dim
#define NG   8192    // segments
#define NEMB 128     // embedding dim
#define NHID 64      // EMB/2
#define ZS   180     // padded smem stride (words) per vocab row: 180%32=20 -> float4 reads spread over all 8 bank-quads

// Scratch (no allocations allowed -> __device__ globals)
__device__ float g_zbase[NVOC * NL * NH];   // [v][l][j] = emb[v,:16] @ w1[l]
__device__ float g_W[NG * NVOC];            // per-(segment, vocab) scale accumulator

// ---------------------------------------------------------------------------
// Kernel 0: zero the accumulator (must happen every graph replay)
// ---------------------------------------------------------------------------
__global__ void zero_kernel() {
    int i = blockIdx.x * blockDim.x + threadIdx.x;
    if (i < NG * NVOC) g_W[i] = 0.f;
}

// ---------------------------------------------------------------------------
// Kernel 1: zbase[v][l][j] = sum_k emb[v][k] * w1[l][k][j]   (k < 16)
// grid = NVOC, block = NL*NH = 160
// ---------------------------------------------------------------------------
__global__ void zbase_kernel(const float* __restrict__ emb,
                             const float* __restrict__ w1) {
    int v = blockIdx.x;
    int t = threadIdx.x;          // 0..159
    int l = t / NH, j = t % NH;
    float acc = 0.f;
#pragma unroll
    for (int k = 0; k < NSD; k++)
        acc = fmaf(emb[v * NEMB + k], w1[(l * NSD + k) * NH + j], acc);
    g_zbase[v * NL * NH + t] = acc;
}

// ---------------------------------------------------------------------------
// Kernel 2: per-node gate loop -> scale; atomically accumulate into W[g][v]
// zbase table lives in shared memory (padded stride ZS for bank spread).
// ---------------------------------------------------------------------------
__global__ void __launch_bounds__(256)
node_kernel(const int* __restrict__ atoms, const int* __restrict__ batch,
            const float* __restrict__ b1, const float* __restrict__ w2,
            const float* __restrict__ b2, int N) {
    extern __shared__ float sm[];
    float* zb  = sm;                       // NVOC*ZS
    float* b1s = sm + NVOC * ZS;           // NL*NH
    float* w2s = b1s + NL * NH;            // NL*NH
    float* b2s = w2s + NL * NH;            // NL

    for (int i = threadIdx.x; i < NVOC * NL * NH; i += blockDim.x) {
        int v = i / (NL * NH);
        int r = i - v * (NL * NH);
        zb[v * ZS + r] = g_zbase[i];
    }
    for (int i = threadIdx.x; i < NL * NH; i += blockDim.x) {
        b1s[i] = b1[i];
        w2s[i] = w2[i];
    }
    if (threadIdx.x < NL) b2s[threadIdx.x] = b2[threadIdx.x];
    __syncthreads();

    int stride = gridDim.x * blockDim.x;
    for (int n = blockIdx.x * blockDim.x + threadIdx.x; n < N; n += stride) {
        int v = atoms[n];
        int g = batch[n];
        float scale = 1.f;
#pragma unroll
        for (int l = 0; l < NL; l++) {
            float acc = b2s[l];
            const float4* zr = reinterpret_cast<const float4*>(zb + v * ZS + l * NH);
            const float4* br = reinterpret_cast<const float4*>(b1s + l * NH);
            const float4* wr = reinterpret_cast<const float4*>(w2s + l * NH);
#pragma unroll
            for (int q = 0; q < NH / 4; q++) {
                float4 z = zr[q];
                float4 b = br[q];
                float4 w = wr[q];
                acc = fmaf(fmaxf(fmaf(scale, z.x, b.x), 0.f), w.x, acc);
                acc = fmaf(fmaxf(fmaf(scale, z.y, b.y), 0.f), w.y, acc);
                acc = fmaf(fmaxf(fmaf(scale, z.z, b.z), 0.f), w.z, acc);
                acc = fmaf(fmaxf(fmaf(scale, z.w, b.w), 0.f), w.w, acc);
            }
            // m = sigmoid(acc); m > 0.5 <=> acc > 0 -> factor 1 (exact)
            // else factor = 1 - m = sigmoid(-acc) = 1/(1+exp(acc))
            if (!(acc > 0.f)) scale *= 1.f / (1.f + expf(acc));
        }
        atomicAdd(&g_W[g * NVOC + v], scale);
    }
}

// ---------------------------------------------------------------------------
// Kernel 3: pooled[g] = W[g] @ emb (100x128), then relu(pooled@pw1+pb1)@pw2+pb2
// One CTA handles SEGS segments; emb + pw1 cached in smem.
// ---------------------------------------------------------------------------
#define SEGS 16
__global__ void __launch_bounds__(128)
pool_kernel(const float* __restrict__ emb, const float* __restrict__ pw1,
            const float* __restrict__ pb1, const float* __restrict__ pw2,
            const float* __restrict__ pb2, float* __restrict__ out) {
    extern __shared__ float sm[];
    float* emb_s    = sm;                       // NVOC*NEMB (12800)
    float* pw1_s    = emb_s + NVOC * NEMB;      // NEMB*NHID (8192)
    float* pb1_s    = pw1_s + NEMB * NHID;      // NHID
    float* pw2_s    = pb1_s + NHID;             // NHID
    float* wrow     = pw2_s + NHID;             // 128 (uses 100)
    float* pooled_s = wrow + 128;               // NEMB
    float* red      = pooled_s + NEMB;          // 2

    int tid = threadIdx.x;
    for (int i = tid; i < NVOC * NEMB; i += 128) emb_s[i] = emb[i];
    for (int i = tid; i < NEMB * NHID; i += 128) pw1_s[i] = pw1[i];
    if (tid < NHID) { pb1_s[tid] = pb1[tid]; pw2_s[tid] = pw2[tid]; }
    float pb2v = pb2[0];
    __syncthreads();

    for (int s = 0; s < SEGS; s++) {
        int g = blockIdx.x * SEGS + s;
        if (tid < NVOC) wrow[tid] = g_W[g * NVOC + tid];
        __syncthreads();

        // pooled[d] = sum_v W[g][v] * emb[v][d]; thread = d
        float p = 0.f;
#pragma unroll 10
        for (int v = 0; v < NVOC; v++)
            p = fmaf(wrow[v], emb_s[v * NEMB + tid], p);
        pooled_s[tid] = p;
        __syncthreads();

        if (tid < NHID) {
            float h = pb1_s[tid];
#pragma unroll 8
            for (int d = 0; d < NEMB; d++)
                h = fmaf(pooled_s[d], pw1_s[d * NHID + tid], h);
            float t = fmaxf(h, 0.f) * pw2_s[tid];
#pragma unroll
            for (int off = 16; off; off >>= 1)
                t += __shfl_down_sync(0xffffffffu, t, off);
            if ((tid & 31) == 0) red[tid >> 5] = t;
        }
        __syncthreads();
        if (tid == 0) out[g] = red[0] + red[1] + pb2v;
        __syncthreads();  // before wrow/pooled_s reuse
    }
}

// ---------------------------------------------------------------------------
// Launch
// ---------------------------------------------------------------------------
extern "C" void kernel_launch(void* const* d_in, const int* in_sizes, int n_in,
                              void* d_out, int out_size) {
    const int*   atoms = (const int*)d_in[0];
    // d_in[1] pos        : UNUSED by reference
    // d_in[2] edge_index : UNUSED by reference
    const int*   batch = (const int*)d_in[3];
    const float* emb   = (const float*)d_in[4];
    const float* w1    = (const float*)d_in[5];
    const float* b1    = (const float*)d_in[6];
    const float* w2    = (const float*)d_in[7];
    const float* b2    = (const float*)d_in[8];
    const float* pw1   = (const float*)d_in[9];
    const float* pb1   = (const float*)d_in[10];
    const float* pw2   = (const float*)d_in[11];
    const float* pb2   = (const float*)d_in[12];
    int N = in_sizes[0];

    size_t smem1 = (size_t)(NVOC * ZS + 2 * NL * NH + NL) * sizeof(float);            // ~73.3 KB
    size_t smem3 = (size_t)(NVOC * NEMB + NEMB * NHID + 2 * NHID + 128 + NEMB + 2) *
                   sizeof(float);                                                      // ~85.5 KB
    cudaFuncSetAttribute(node_kernel, cudaFuncAttributeMaxDynamicSharedMemorySize,
                         (int)smem1);
    cudaFuncSetAttribute(pool_kernel, cudaFuncAttributeMaxDynamicSharedMemorySize,
                         (int)smem3);

    zero_kernel<<<(NG * NVOC + 255) / 256, 256>>>();
    zbase_kernel<<<NVOC, NL * NH>>>(emb, w1);
    node_kernel<<<456, 256, smem1>>>(atoms, batch, b1, w2, b2, N);
    pool_kernel<<<NG / SEGS, 128, smem3>>>(emb, pw1, pb1, pw2, pb2, (float*)d_out);
}

// round 10
// speedup vs baseline: 4.4485x; 4.4485x over previous
#include <cuda_runtime.h>

// Problem constants (fixed-shape problem)
#define NVOC 100     // vocab
#define NL   5       // gate layers
#define NH   32      // gate hidden
#define NSD  16      // s-dim
#define NG   8192    // segments
#define NEMB 128     // embedding dim
#define NHID 64      // EMB/2

// Scratch (__device__ globals; no allocations allowed)
__device__ float g_scale[NVOC];          // per-vocab final gate product
__device__ float g_E1[NVOC * NHID];      // emb @ pw1  (100 x 64)
__device__ float g_W[NG * NVOC];         // per-(segment, vocab) scale accumulator

// ---------------------------------------------------------------------------
// Kernel 0: zero the accumulator (every graph replay)
// ---------------------------------------------------------------------------
__global__ void zero_kernel() {
    int i = blockIdx.x * blockDim.x + threadIdx.x;          // 819200/4 elems
    reinterpret_cast<float4*>(g_W)[i] = make_float4(0.f, 0.f, 0.f, 0.f);
}

// ---------------------------------------------------------------------------
// Kernel 1: scale[v] = product over layers of the gate factor.
// Entire cascade is a function of vocab id only (h scales uniformly).
// grid = NVOC, block = 32 (lane = hidden unit j)
// ---------------------------------------------------------------------------
__global__ void scale_kernel(const float* __restrict__ emb,
                             const float* __restrict__ w1,
                             const float* __restrict__ b1,
                             const float* __restrict__ w2,
                             const float* __restrict__ b2) {
    int v = blockIdx.x, j = threadIdx.x;
    float e[NSD];
#pragma unroll
    for (int k = 0; k < NSD; k++) e[k] = emb[v * NEMB + k];

    float scale = 1.f;
#pragma unroll
    for (int l = 0; l < NL; l++) {
        float zb = 0.f;
#pragma unroll
        for (int k = 0; k < NSD; k++)
            zb = fmaf(e[k], w1[(l * NSD + k) * NH + j], zb);
        float t = fmaxf(fmaf(scale, zb, b1[l * NH + j]), 0.f) * w2[l * NH + j];
#pragma unroll
        for (int o = 16; o; o >>= 1) t += __shfl_xor_sync(0xffffffffu, t, o);
        float acc = t + b2[l];
        // m = sigmoid(acc); m>0.5 <=> acc>0 -> factor 1 (exact).
        // else factor = 1-m = 1/(1+exp(acc))
        if (!(acc > 0.f)) scale *= 1.f / (1.f + expf(acc));
    }
    if (j == 0) g_scale[v] = scale;
}

// ---------------------------------------------------------------------------
// Kernel 2: E1[v][j] = sum_d emb[v][d] * pw1[d][j]
// grid = NVOC, block = NHID
// ---------------------------------------------------------------------------
__global__ void e1_kernel(const float* __restrict__ emb,
                          const float* __restrict__ pw1) {
    int v = blockIdx.x, j = threadIdx.x;
    float a0 = 0.f, a1 = 0.f, a2 = 0.f, a3 = 0.f;
#pragma unroll
    for (int d = 0; d < NEMB; d += 4) {
        a0 = fmaf(emb[v * NEMB + d + 0], pw1[(d + 0) * NHID + j], a0);
        a1 = fmaf(emb[v * NEMB + d + 1], pw1[(d + 1) * NHID + j], a1);
        a2 = fmaf(emb[v * NEMB + d + 2], pw1[(d + 2) * NHID + j], a2);
        a3 = fmaf(emb[v * NEMB + d + 3], pw1[(d + 3) * NHID + j], a3);
    }
    g_E1[v * NHID + j] = (a0 + a1) + (a2 + a3);
}

// ---------------------------------------------------------------------------
// Kernel 3: W[g][v] += scale[v] for every node. Pure gather + RED.ADD.
// ---------------------------------------------------------------------------
__global__ void __launch_bounds__(256)
node_kernel(const int* __restrict__ atoms, const int* __restrict__ batch, int N) {
    __shared__ float s_scale[NVOC];
    int tid = threadIdx.x;
    if (tid < NVOC) s_scale[tid] = g_scale[tid];
    __syncthreads();

    int n4 = N >> 2;
    int i = blockIdx.x * blockDim.x + tid;
    if (i < n4) {
        int4 a = reinterpret_cast<const int4*>(atoms)[i];
        int4 b = reinterpret_cast<const int4*>(batch)[i];
        atomicAdd(&g_W[b.x * NVOC + a.x], s_scale[a.x]);
        atomicAdd(&g_W[b.y * NVOC + a.y], s_scale[a.y]);
        atomicAdd(&g_W[b.z * NVOC + a.z], s_scale[a.z]);
        atomicAdd(&g_W[b.w * NVOC + a.w], s_scale[a.w]);
    }
    if (blockIdx.x == 0 && tid == 0) {       // tail (N % 4)
        for (int n = n4 * 4; n < N; n++)
            atomicAdd(&g_W[batch[n] * NVOC + atoms[n]], s_scale[atoms[n]]);
    }
}

// ---------------------------------------------------------------------------
// Kernel 4: out[g] = relu(W[g] @ E1 + pb1) @ pw2 + pb2
// Warp-per-segment; E1 in smem; no CTA barriers in the hot loop.
// ---------------------------------------------------------------------------
__global__ void __launch_bounds__(256)
pool_kernel(const float* __restrict__ pb1, const float* __restrict__ pw2,
            const float* __restrict__ pb2, float* __restrict__ out) {
    __shared__ float E1s[NVOC * NHID];       // 25.6 KB
    __shared__ float pb1s[NHID], pw2s[NHID];
    __shared__ float wrow[8][NVOC];

    int tid = threadIdx.x;
    for (int i = tid; i < NVOC * NHID; i += 256) E1s[i] = g_E1[i];
    if (tid < NHID) { pb1s[tid] = pb1[tid]; pw2s[tid] = pw2[tid]; }
    float pb2v = pb2[0];
    __syncthreads();

    int warp = tid >> 5, lane = tid & 31;
    int nwarps = gridDim.x * 8;
    const float2* E2 = reinterpret_cast<const float2*>(E1s);

    for (int g = blockIdx.x * 8 + warp; g < NG; g += nwarps) {
        const float* Wg = g_W + g * NVOC;
        wrow[warp][lane]      = Wg[lane];
        wrow[warp][32 + lane] = Wg[32 + lane];
        wrow[warp][64 + lane] = Wg[64 + lane];
        if (lane < 4) wrow[warp][96 + lane] = Wg[96 + lane];
        __syncwarp();

        float accx = pb1s[2 * lane], accy = pb1s[2 * lane + 1];
#pragma unroll 5
        for (int v = 0; v < NVOC; v++) {
            float wv = wrow[warp][v];            // broadcast
            float2 e = E2[v * 32 + lane];        // conflict-free
            accx = fmaf(wv, e.x, accx);
            accy = fmaf(wv, e.y, accy);
        }
        float t = fmaf(fmaxf(accx, 0.f), pw2s[2 * lane],
                       fmaxf(accy, 0.f) * pw2s[2 * lane + 1]);
#pragma unroll
        for (int o = 16; o; o >>= 1) t += __shfl_down_sync(0xffffffffu, t, o);
        if (lane == 0) out[g] = t + pb2v;
        __syncwarp();                            // before wrow reuse
    }
}

// ---------------------------------------------------------------------------
// Launch
// ---------------------------------------------------------------------------
extern "C" void kernel_launch(void* const* d_in, const int* in_sizes, int n_in,
                              void* d_out, int out_size) {
    const int*   atoms = (const int*)d_in[0];
    // d_in[1] pos        : UNUSED by reference
    // d_in[2] edge_index : UNUSED by reference
    const int*   batch = (const int*)d_in[3];
    const float* emb   = (const float*)d_in[4];
    const float* w1    = (const float*)d_in[5];
    const float* b1    = (const float*)d_in[6];
    const float* w2    = (const float*)d_in[7];
    const float* b2    = (const float*)d_in[8];
    const float* pw1   = (const float*)d_in[9];
    const float* pb1   = (const float*)d_in[10];
    const float* pw2   = (const float*)d_in[11];
    const float* pb2   = (const float*)d_in[12];
    int N = in_sizes[0];

    zero_kernel<<<(NG * NVOC / 4) / 256, 256>>>();               // 800 CTAs
    scale_kernel<<<NVOC, 32>>>(emb, w1, b1, w2, b2);
    e1_kernel<<<NVOC, NHID>>>(emb, pw1);
    node_kernel<<<((N >> 2) + 255) / 256, 256>>>(atoms, batch, N);
    pool_kernel<<<512, 256>>>(pb1, pw2, pb2, (float*)d_out);
}